// round 1
// baseline (speedup 1.0000x reference)
#include <cuda_runtime.h>
#include <math.h>

#define DIMV 512
#define BATCH 8
#define QROWS 1024   // QS*QT = 64*16
#define KROWS 4096   // KS*KT = 256*16
#define RANKV 32
#define MAXNK 144    // 9 kv-steps * 16

// -------- scratch (device globals; no allocation allowed) --------
__device__ float g_gb[BATCH * 2 * DIMV];            // gamma | beta per batch
__device__ float g_qmod[BATCH * QROWS * DIMV];      // LN+FiLM(q)
__device__ float g_snorm[BATCH * KROWS * DIMV];     // LN(s)
__device__ float g_qp[BATCH * QROWS * DIMV];
__device__ float g_kp[BATCH * KROWS * DIMV];
__device__ float g_vp[BATCH * KROWS * DIMV];
__device__ float g_gq[BATCH * QROWS * RANKV];
__device__ float g_gk[BATCH * KROWS * RANKV];
__device__ float g_ctx[BATCH * QROWS * DIMV];

__device__ __forceinline__ float warp_sum(float v) {
    #pragma unroll
    for (int o = 16; o; o >>= 1) v += __shfl_xor_sync(0xffffffffu, v, o);
    return v;
}

// -------- context / FiLM head: h = silu(ctx0@Wc0 + ctx1@Wc1 + bc0 + bc1); gb = h@Wf + bf --------
__global__ void ctx_kernel(const float* __restrict__ ctx0, const float* __restrict__ ctx1,
                           const float* __restrict__ Wc0, const float* __restrict__ bc0,
                           const float* __restrict__ Wc1, const float* __restrict__ bc1,
                           const float* __restrict__ Wf, const float* __restrict__ bf) {
    int b = blockIdx.x;
    int d = threadIdx.x; // 512 threads
    __shared__ float c0[DIMV], c1[DIMV], h[DIMV];
    c0[d] = ctx0[b * DIMV + d];
    c1[d] = ctx1[b * DIMV + d];
    __syncthreads();
    float acc = bc0[d] + bc1[d];
    #pragma unroll 4
    for (int i = 0; i < DIMV; i++) {
        acc += c0[i] * Wc0[i * DIMV + d];
        acc += c1[i] * Wc1[i * DIMV + d];
    }
    h[d] = acc / (1.f + expf(-acc)); // silu
    __syncthreads();
    #pragma unroll
    for (int j = d; j < 2 * DIMV; j += DIMV) {
        float a = bf[j];
        #pragma unroll 4
        for (int i = 0; i < DIMV; i++) a += h[i] * Wf[i * 2 * DIMV + j];
        g_gb[b * 2 * DIMV + j] = a;
    }
}

// -------- layernorm (+ optional FiLM for q path) --------
__global__ void ln_kernel(const float* __restrict__ x, const float* __restrict__ gw,
                          const float* __restrict__ bw, float* __restrict__ out, int film) {
    int row = blockIdx.x;
    int tid = threadIdx.x; // 256
    const float* xr = x + (size_t)row * DIMV;
    float v0 = xr[tid], v1 = xr[tid + 256];
    float s = v0 + v1;
    float ss = v0 * v0 + v1 * v1;
    __shared__ float rs[8], rq[8];
    float ws = warp_sum(s), wq = warp_sum(ss);
    int lane = tid & 31, w = tid >> 5;
    if (lane == 0) { rs[w] = ws; rq[w] = wq; }
    __syncthreads();
    if (w == 0) {
        float a = (lane < 8) ? rs[lane] : 0.f;
        float b2 = (lane < 8) ? rq[lane] : 0.f;
        a = warp_sum(a); b2 = warp_sum(b2);
        if (lane == 0) { rs[0] = a; rq[0] = b2; }
    }
    __syncthreads();
    float mu = rs[0] * (1.f / DIMV);
    float var = rq[0] * (1.f / DIMV) - mu * mu;
    float rstd = rsqrtf(var + 1e-5f);
    const float* gam = g_gb + (film ? (row >> 10) * 2 * DIMV : 0);
    #pragma unroll
    for (int e = 0; e < 2; e++) {
        int d = tid + e * 256;
        float v = e ? v1 : v0;
        float y = (v - mu) * rstd * gw[d] + bw[d];
        if (film) y = y * (1.f + gam[d]) + gam[DIMV + d];
        out[(size_t)row * DIMV + d] = y;
    }
}

// -------- fp32 tiled GEMM: C[M,N] = A[M,K] @ B[K,N] + bias[N] (64x64x16, 4x4/thread) --------
__global__ void gemm64(const float* __restrict__ A, const float* __restrict__ Bm,
                       const float* __restrict__ bias, float* __restrict__ C,
                       int M, int N, int K) {
    __shared__ float As[16][64];  // [k][m]
    __shared__ float Bs[16][64];  // [k][n]
    int tid = threadIdx.x;
    int bm = blockIdx.y * 64;
    int bn = blockIdx.x * 64;
    int tx = tid & 15, ty = tid >> 4;
    int arow = tid >> 2;          // 0..63
    int acol = (tid & 3) * 4;     // 0,4,8,12
    int brow = tid >> 4;          // 0..15
    int bcol = (tid & 15) * 4;    // 0..60
    float acc[4][4] = {};
    for (int k0 = 0; k0 < K; k0 += 16) {
        float4 av = *(const float4*)(A + (size_t)(bm + arow) * K + k0 + acol);
        As[acol + 0][arow] = av.x;
        As[acol + 1][arow] = av.y;
        As[acol + 2][arow] = av.z;
        As[acol + 3][arow] = av.w;
        *(float4*)(&Bs[brow][bcol]) = *(const float4*)(Bm + (size_t)(k0 + brow) * N + bn + bcol);
        __syncthreads();
        #pragma unroll
        for (int k = 0; k < 16; k++) {
            float4 a4 = *(const float4*)(&As[k][ty * 4]);
            float4 b4 = *(const float4*)(&Bs[k][tx * 4]);
            float ar[4] = {a4.x, a4.y, a4.z, a4.w};
            float br[4] = {b4.x, b4.y, b4.z, b4.w};
            #pragma unroll
            for (int i = 0; i < 4; i++)
                #pragma unroll
                for (int j = 0; j < 4; j++)
                    acc[i][j] += ar[i] * br[j];
        }
        __syncthreads();
    }
    #pragma unroll
    for (int i = 0; i < 4; i++) {
        int r = bm + ty * 4 + i;
        #pragma unroll
        for (int j = 0; j < 4; j++) {
            int c = bn + tx * 4 + j;
            C[(size_t)r * N + c] = acc[i][j] + bias[c];
        }
    }
}

// -------- skinny gate GEMM: G[M,32] = A[M,512] @ Wg[512,32] --------
__global__ void gate_gemm(const float* __restrict__ A, const float* __restrict__ Wg,
                          float* __restrict__ G) {
    int row = blockIdx.x * 8 + (threadIdx.x >> 5);
    int col = threadIdx.x & 31;
    const float* a = A + (size_t)row * DIMV;
    float acc = 0.f;
    #pragma unroll 8
    for (int k = 0; k < DIMV; k++)
        acc += a[k] * Wg[k * RANKV + col];
    G[(size_t)row * RANKV + col] = acc;
}

// -------- block-sparse attention: one CTA per (b, q-step) --------
__global__ void attn_kernel(const float* __restrict__ mask) {
    int qs = blockIdx.x;   // 0..63
    int bb = blockIdx.y;   // 0..7
    int tid = threadIdx.x; // 256
    __shared__ float sc[16][MAXNK];
    __shared__ int s_lo, s_hi;
    if (tid == 0) { s_lo = 256; s_hi = -1; }
    __syncthreads();
    {
        float mv = mask[(size_t)(qs * 16) * KROWS + tid * 16];
        if (mv == 0.0f) { atomicMin(&s_lo, tid); atomicMax(&s_hi, tid); }
    }
    __syncthreads();
    int kbase = s_lo * 16;
    int nk = (s_hi - s_lo + 1) * 16;   // <= 144

    const float* qp = g_qp + ((size_t)bb * QROWS + qs * 16) * DIMV;
    const float* kp = g_kp + ((size_t)bb * KROWS + kbase) * DIMV;
    const float* gq = g_gq + ((size_t)bb * QROWS + qs * 16) * RANKV;
    const float* gk = g_gk + ((size_t)bb * KROWS + kbase) * RANKV;
    int tx = tid & 15, ty = tid >> 4;
    const float SCALE = 0.04419417382415922f;   // 512^-0.5
    const float GSCALE = 0.17677669529663687f;  // 32^-0.5

    const float* qrow = qp + ty * DIMV;
    const float* grow = gq + ty * RANKV;
    for (int kj = tx; kj < nk; kj += 16) {
        const float* krow = kp + (size_t)kj * DIMV;
        float s = 0.f;
        #pragma unroll 4
        for (int k = 0; k < DIMV; k += 4) {
            float4 q4 = *(const float4*)(qrow + k);
            float4 k4 = *(const float4*)(krow + k);
            s += q4.x * k4.x + q4.y * k4.y + q4.z * k4.z + q4.w * k4.w;
        }
        const float* gkr = gk + kj * RANKV;
        float gl = 0.f;
        #pragma unroll
        for (int r = 0; r < RANKV; r += 4) {
            float4 a4 = *(const float4*)(grow + r);
            float4 b4 = *(const float4*)(gkr + r);
            gl += a4.x * b4.x + a4.y * b4.y + a4.z * b4.z + a4.w * b4.w;
        }
        gl *= GSCALE;
        float sig = 1.f / (1.f + expf(-gl));
        sc[ty][kj] = s * SCALE + logf(sig + 1e-6f);
    }
    __syncthreads();

    // softmax per row ty across its 16 tx lanes (valid region only; masked cols excluded)
    float m = -1e30f;
    for (int kj = tx; kj < nk; kj += 16) m = fmaxf(m, sc[ty][kj]);
    #pragma unroll
    for (int o = 8; o; o >>= 1) m = fmaxf(m, __shfl_xor_sync(0xffffffffu, m, o, 16));
    float sum = 0.f;
    for (int kj = tx; kj < nk; kj += 16) {
        float e = expf(sc[ty][kj] - m);
        sc[ty][kj] = e;
        sum += e;
    }
    #pragma unroll
    for (int o = 8; o; o >>= 1) sum += __shfl_xor_sync(0xffffffffu, sum, o, 16);
    float inv = 1.f / sum;
    for (int kj = tx; kj < nk; kj += 16) sc[ty][kj] *= inv;
    __syncthreads();

    // AV: each thread owns 2 dims, accumulates all 16 q rows
    const float* vp = g_vp + ((size_t)bb * KROWS + kbase) * DIMV;
    float acc0[16], acc1[16];
    #pragma unroll
    for (int i = 0; i < 16; i++) { acc0[i] = 0.f; acc1[i] = 0.f; }
    int d0 = tid, d1 = tid + 256;
    for (int kj = 0; kj < nk; kj++) {
        float v0 = vp[(size_t)kj * DIMV + d0];
        float v1 = vp[(size_t)kj * DIMV + d1];
        #pragma unroll
        for (int qi = 0; qi < 16; qi++) {
            float p = sc[qi][kj];
            acc0[qi] += p * v0;
            acc1[qi] += p * v1;
        }
    }
    float* ctx = g_ctx + ((size_t)bb * QROWS + qs * 16) * DIMV;
    #pragma unroll
    for (int qi = 0; qi < 16; qi++) {
        ctx[(size_t)qi * DIMV + d0] = acc0[qi];
        ctx[(size_t)qi * DIMV + d1] = acc1[qi];
    }
}

extern "C" void kernel_launch(void* const* d_in, const int* in_sizes, int n_in,
                              void* d_out, int out_size) {
    const float* query = (const float*)d_in[0];
    const float* source = (const float*)d_in[1];
    const float* ctx0  = (const float*)d_in[2];
    const float* ctx1  = (const float*)d_in[3];
    const float* mask  = (const float*)d_in[4];
    const float* qn_g  = (const float*)d_in[5];
    const float* qn_b  = (const float*)d_in[6];
    const float* kvn_g = (const float*)d_in[7];
    const float* kvn_b = (const float*)d_in[8];
    const float* Wq = (const float*)d_in[9];
    const float* bq = (const float*)d_in[10];
    const float* Wk = (const float*)d_in[11];
    const float* bk = (const float*)d_in[12];
    const float* Wv = (const float*)d_in[13];
    const float* bv = (const float*)d_in[14];
    const float* Wo = (const float*)d_in[15];
    const float* bo = (const float*)d_in[16];
    const float* Wgq = (const float*)d_in[17];
    const float* Wgk = (const float*)d_in[18];
    const float* Wc0 = (const float*)d_in[19];
    const float* bc0 = (const float*)d_in[20];
    const float* Wc1 = (const float*)d_in[21];
    const float* bc1 = (const float*)d_in[22];
    const float* Wf = (const float*)d_in[23];
    const float* bf = (const float*)d_in[24];
    float* out = (float*)d_out;

    float *qmod, *snorm, *qp, *kp, *vp, *gq, *gk, *ctxb;
    cudaGetSymbolAddress((void**)&qmod, g_qmod);
    cudaGetSymbolAddress((void**)&snorm, g_snorm);
    cudaGetSymbolAddress((void**)&qp, g_qp);
    cudaGetSymbolAddress((void**)&kp, g_kp);
    cudaGetSymbolAddress((void**)&vp, g_vp);
    cudaGetSymbolAddress((void**)&gq, g_gq);
    cudaGetSymbolAddress((void**)&gk, g_gk);
    cudaGetSymbolAddress((void**)&ctxb, g_ctx);

    // 1. FiLM head
    ctx_kernel<<<BATCH, DIMV>>>(ctx0, ctx1, Wc0, bc0, Wc1, bc1, Wf, bf);
    // 2. LayerNorms
    ln_kernel<<<BATCH * QROWS, 256>>>(query, qn_g, qn_b, qmod, 1);
    ln_kernel<<<BATCH * KROWS, 256>>>(source, kvn_g, kvn_b, snorm, 0);
    // 3. Projections
    dim3 gridQ(DIMV / 64, BATCH * QROWS / 64);
    dim3 gridK(DIMV / 64, BATCH * KROWS / 64);
    gemm64<<<gridQ, 256>>>(qmod, Wq, bq, qp, BATCH * QROWS, DIMV, DIMV);
    gemm64<<<gridK, 256>>>(snorm, Wk, bk, kp, BATCH * KROWS, DIMV, DIMV);
    gemm64<<<gridK, 256>>>(snorm, Wv, bv, vp, BATCH * KROWS, DIMV, DIMV);
    // 4. Gate projections
    gate_gemm<<<BATCH * QROWS / 8, 256>>>(qp, Wgq, gq);
    gate_gemm<<<BATCH * KROWS / 8, 256>>>(kp, Wgk, gk);
    // 5. Block-sparse attention
    attn_kernel<<<dim3(64, BATCH), 256>>>(mask);
    // 6. Output projection
    gemm64<<<gridQ, 256>>>(ctxb, Wo, bo, out, BATCH * QROWS, DIMV, DIMV);
}

// round 3
// speedup vs baseline: 1.6267x; 1.6267x over previous
#include <cuda_runtime.h>
#include <cuda_bf16.h>
#include <math.h>
#include <stdint.h>

#define DIMV 512
#define BATCH 8
#define QROWS 1024   // QS*QT = 64*16
#define KROWS 4096   // KS*KT = 256*16
#define RANKV 32
#define MAXNK 144    // 9 kv-steps * 16

// ---------------- scratch (device globals; no allocation allowed) ----------------
__device__ float g_gb[BATCH * 2 * DIMV];                    // gamma | beta per batch
__device__ __nv_bfloat16 g_qhi[BATCH * QROWS * DIMV];       // LN+FiLM(q) hi
__device__ __nv_bfloat16 g_qlo[BATCH * QROWS * DIMV];       // LN+FiLM(q) lo
__device__ __nv_bfloat16 g_shi[BATCH * KROWS * DIMV];       // LN(s) hi
__device__ __nv_bfloat16 g_slo[BATCH * KROWS * DIMV];       // LN(s) lo
__device__ __nv_bfloat16 g_chi[BATCH * QROWS * DIMV];       // attn ctx hi
__device__ __nv_bfloat16 g_clo[BATCH * QROWS * DIMV];       // attn ctx lo
__device__ __nv_bfloat16 g_wthi[4 * DIMV * DIMV];           // W^T hi (q,k,v,o) [n][k]
__device__ __nv_bfloat16 g_wtlo[4 * DIMV * DIMV];           // W^T lo
__device__ float g_qp[BATCH * QROWS * DIMV];
__device__ float g_kp[BATCH * KROWS * DIMV];
__device__ float g_vp[BATCH * KROWS * DIMV];
__device__ float g_gq[BATCH * QROWS * RANKV];
__device__ float g_gk[BATCH * KROWS * RANKV];

__device__ __forceinline__ uint32_t smem_u32(const void* p) {
    uint32_t a;
    asm("{ .reg .u64 t; cvta.to.shared.u64 t, %1; cvt.u32.u64 %0, t; }" : "=r"(a) : "l"(p));
    return a;
}
__device__ __forceinline__ void cp16(uint32_t s, const void* g) {
    asm volatile("cp.async.cg.shared.global [%0], [%1], 16;" :: "r"(s), "l"(g));
}
__device__ __forceinline__ void cp_commit() {
    asm volatile("cp.async.commit_group;" ::: "memory");
}
__device__ __forceinline__ void cp_wait0() {
    asm volatile("cp.async.wait_group 0;" ::: "memory");
}
__device__ __forceinline__ void ldm_x4(uint32_t* r, uint32_t addr) {
    asm volatile("ldmatrix.sync.aligned.m8n8.x4.shared.b16 {%0,%1,%2,%3}, [%4];"
                 : "=r"(r[0]), "=r"(r[1]), "=r"(r[2]), "=r"(r[3]) : "r"(addr));
}
__device__ __forceinline__ void mma16816(float* c, const uint32_t* a, uint32_t b0, uint32_t b1) {
    asm volatile(
        "mma.sync.aligned.m16n8k16.row.col.f32.bf16.bf16.f32 "
        "{%0,%1,%2,%3}, {%4,%5,%6,%7}, {%8,%9}, {%0,%1,%2,%3};"
        : "+f"(c[0]), "+f"(c[1]), "+f"(c[2]), "+f"(c[3])
        : "r"(a[0]), "r"(a[1]), "r"(a[2]), "r"(a[3]), "r"(b0), "r"(b1));
}

__device__ __forceinline__ float warp_sum(float v) {
    #pragma unroll
    for (int o = 16; o; o >>= 1) v += __shfl_xor_sync(0xffffffffu, v, o);
    return v;
}

// ---------------- weight transpose + bf16 hi/lo split ----------------
__global__ void wsplit_kernel(const float* __restrict__ Wq, const float* __restrict__ Wk,
                              const float* __restrict__ Wv, const float* __restrict__ Wo) {
    __shared__ float t[32][33];
    const float* W = (blockIdx.z == 0) ? Wq : (blockIdx.z == 1) ? Wk
                   : (blockIdx.z == 2) ? Wv : Wo;
    __nv_bfloat16* whi = g_wthi + (size_t)blockIdx.z * DIMV * DIMV;
    __nv_bfloat16* wlo = g_wtlo + (size_t)blockIdx.z * DIMV * DIMV;
    int tx = threadIdx.x, ty = threadIdx.y;   // (32, 8)
    int n0 = blockIdx.x * 32, k0 = blockIdx.y * 32;
    for (int r = ty; r < 32; r += 8)
        t[r][tx] = W[(size_t)(k0 + r) * DIMV + n0 + tx];
    __syncthreads();
    for (int r = ty; r < 32; r += 8) {
        float v = t[tx][r];                   // = W[k0+tx][n0+r]
        __nv_bfloat16 h = __float2bfloat16(v);
        size_t idx = (size_t)(n0 + r) * DIMV + k0 + tx;
        whi[idx] = h;
        wlo[idx] = __float2bfloat16(v - __bfloat162float(h));
    }
}

// ---------------- context / FiLM head ----------------
__global__ void ctx_kernel(const float* __restrict__ ctx0, const float* __restrict__ ctx1,
                           const float* __restrict__ Wc0, const float* __restrict__ bc0,
                           const float* __restrict__ Wc1, const float* __restrict__ bc1,
                           const float* __restrict__ Wf, const float* __restrict__ bf) {
    int b = blockIdx.x;
    int d = threadIdx.x;
    __shared__ float c0[DIMV], c1[DIMV], h[DIMV];
    c0[d] = ctx0[b * DIMV + d];
    c1[d] = ctx1[b * DIMV + d];
    __syncthreads();
    float acc = bc0[d] + bc1[d];
    #pragma unroll 4
    for (int i = 0; i < DIMV; i++) {
        acc += c0[i] * Wc0[i * DIMV + d];
        acc += c1[i] * Wc1[i * DIMV + d];
    }
    h[d] = acc / (1.f + expf(-acc));
    __syncthreads();
    #pragma unroll
    for (int j = d; j < 2 * DIMV; j += DIMV) {
        float a = bf[j];
        #pragma unroll 4
        for (int i = 0; i < DIMV; i++) a += h[i] * Wf[i * 2 * DIMV + j];
        g_gb[b * 2 * DIMV + j] = a;
    }
}

// ---------------- layernorm (+FiLM) -> bf16 hi/lo ----------------
__global__ void ln_kernel(const float* __restrict__ x, const float* __restrict__ gw,
                          const float* __restrict__ bw,
                          __nv_bfloat16* __restrict__ ohi, __nv_bfloat16* __restrict__ olo,
                          int film) {
    int row = blockIdx.x;
    int tid = threadIdx.x; // 256
    const float* xr = x + (size_t)row * DIMV;
    float v0 = xr[tid], v1 = xr[tid + 256];
    float s = v0 + v1;
    float ss = v0 * v0 + v1 * v1;
    __shared__ float rs[8], rq[8];
    float ws = warp_sum(s), wq = warp_sum(ss);
    int lane = tid & 31, w = tid >> 5;
    if (lane == 0) { rs[w] = ws; rq[w] = wq; }
    __syncthreads();
    if (w == 0) {
        float a = (lane < 8) ? rs[lane] : 0.f;
        float b2 = (lane < 8) ? rq[lane] : 0.f;
        a = warp_sum(a); b2 = warp_sum(b2);
        if (lane == 0) { rs[0] = a; rq[0] = b2; }
    }
    __syncthreads();
    float mu = rs[0] * (1.f / DIMV);
    float var = rq[0] * (1.f / DIMV) - mu * mu;
    float rstd = rsqrtf(var + 1e-5f);
    const float* gam = g_gb + (film ? (row >> 10) * 2 * DIMV : 0);
    #pragma unroll
    for (int e = 0; e < 2; e++) {
        int d = tid + e * 256;
        float v = e ? v1 : v0;
        float y = (v - mu) * rstd * gw[d] + bw[d];
        if (film) y = y * (1.f + gam[d]) + gam[DIMV + d];
        __nv_bfloat16 h = __float2bfloat16(y);
        ohi[(size_t)row * DIMV + d] = h;
        olo[(size_t)row * DIMV + d] = __float2bfloat16(y - __bfloat162float(h));
    }
}

// ---------------- mma.sync bf16x3 GEMM ----------------
// out[M,512] = A[M,512] @ Wt^T + bias, A and Wt both [row][K] bf16 row-major.
// CTA tile 128x128, BK=64, 8 warps (4x2), warp tile 32x64, double-buffered cp.async.
#define BK 64
#define A_STG 16384              // 128 x 64 x 2 bytes
#define STAGE 32768              // A + B
#define GEMM_SMEM (2 * STAGE)    // 64 KB
#define NCHUNK 24                // 8 k-chunks x 3 passes

__global__ void __launch_bounds__(256) mma_gemm(
    const __nv_bfloat16* a0hi, const __nv_bfloat16* a0lo,
    const __nv_bfloat16* b0hi, const __nv_bfloat16* b0lo,
    const float* bias0, float* out0, int nt0,
    const __nv_bfloat16* a1hi, const __nv_bfloat16* a1lo,
    const __nv_bfloat16* b1hi, const __nv_bfloat16* b1lo,
    const float* bias1, float* out1, int nt1,
    const __nv_bfloat16* a2hi, const __nv_bfloat16* a2lo,
    const __nv_bfloat16* b2hi, const __nv_bfloat16* b2lo,
    const float* bias2, float* out2)
{
    extern __shared__ char smem[];
    const uint32_t sbase = smem_u32(smem);
    int tid = threadIdx.x;
    int wid = tid >> 5, lane = tid & 31;

    int id = blockIdx.x;
    const __nv_bfloat16 *ahi, *alo, *bhi, *blo;
    const float* bias; float* outp; int tile;
    if (id < nt0)            { ahi=a0hi; alo=a0lo; bhi=b0hi; blo=b0lo; bias=bias0; outp=out0; tile=id; }
    else if (id < nt0 + nt1) { ahi=a1hi; alo=a1lo; bhi=b1hi; blo=b1lo; bias=bias1; outp=out1; tile=id-nt0; }
    else                     { ahi=a2hi; alo=a2lo; bhi=b2hi; blo=b2lo; bias=bias2; outp=out2; tile=id-nt0-nt1; }
    size_t mrow0 = (size_t)(tile >> 2) * 128;
    int ncol0 = (tile & 3) * 128;
    bhi += (size_t)ncol0 * DIMV;
    blo += (size_t)ncol0 * DIMV;
    bias += ncol0;

    // per-thread load indices (4 units of 16B each for A and B per chunk)
    int lrow = tid >> 3;           // 0..31 (+32 per step)
    int lseg = tid & 7;            // 16B segment within 128B row
    uint32_t soffL[4];
    #pragma unroll
    for (int i = 0; i < 4; i++) {
        uint32_t off = (lrow + i * 32) * 128 + lseg * 16;
        soffL[i] = off ^ ((off >> 3) & 0x70);
    }

    // warp fragment geometry
    int wm = wid & 3, wn = wid >> 2;
    int arow0 = wm * 32 + (lane & 15);
    uint32_t aKby = ((lane >> 4) << 3) * 2;         // 0 or 16 bytes
    uint32_t axor = (arow0 & 7) << 4;
    int brow0 = wn * 64 + ((lane >> 4) << 3) + (lane & 7);
    uint32_t bKby = (((lane >> 3) & 1) << 3) * 2;   // 0 or 16 bytes
    uint32_t bxor = (brow0 & 7) << 4;

    float acc[2][8][4];
    #pragma unroll
    for (int t = 0; t < 2; t++)
        #pragma unroll
        for (int n = 0; n < 8; n++)
            #pragma unroll
            for (int j = 0; j < 4; j++) acc[t][n][j] = 0.f;

    // prologue: load chunk 0 into buf 0
    {
        const __nv_bfloat16* A = ahi;
        const __nv_bfloat16* B = bhi;
        #pragma unroll
        for (int i = 0; i < 4; i++) {
            int row = lrow + i * 32;
            cp16(sbase + soffL[i], A + (mrow0 + row) * DIMV + lseg * 8);
            cp16(sbase + A_STG + soffL[i], B + (size_t)row * DIMV + lseg * 8);
        }
        cp_commit();
    }

    for (int c = 0; c < NCHUNK; c++) {
        int buf = c & 1;
        cp_wait0();
        __syncthreads();
        if (c + 1 < NCHUNK) {
            int cn = c + 1;
            int pass = cn >> 3;
            int k0 = (cn & 7) * BK;
            const __nv_bfloat16* A = (pass == 2) ? alo : ahi;
            const __nv_bfloat16* B = (pass == 1) ? blo : bhi;
            uint32_t dst = sbase + (buf ^ 1) * STAGE;
            #pragma unroll
            for (int i = 0; i < 4; i++) {
                int row = lrow + i * 32;
                cp16(dst + soffL[i], A + (mrow0 + row) * DIMV + k0 + lseg * 8);
                cp16(dst + A_STG + soffL[i], B + (size_t)row * DIMV + k0 + lseg * 8);
            }
            cp_commit();
        }
        uint32_t sa = sbase + buf * STAGE;
        uint32_t sb = sa + A_STG;
        #pragma unroll
        for (int ks = 0; ks < 4; ks++) {
            uint32_t a[2][4];
            #pragma unroll
            for (int t = 0; t < 2; t++)
                ldm_x4(a[t], sa + (uint32_t)(arow0 + t * 16) * 128 + ((ks * 32 + aKby) ^ axor));
            uint32_t b[4][4];
            #pragma unroll
            for (int p = 0; p < 4; p++)
                ldm_x4(b[p], sb + (uint32_t)(brow0 + p * 16) * 128 + ((ks * 32 + bKby) ^ bxor));
            #pragma unroll
            for (int t = 0; t < 2; t++)
                #pragma unroll
                for (int n = 0; n < 8; n++)
                    mma16816(acc[t][n], a[t], b[n >> 1][(n & 1) * 2], b[n >> 1][(n & 1) * 2 + 1]);
        }
    }

    // epilogue: direct global stores with bias
    #pragma unroll
    for (int t = 0; t < 2; t++) {
        size_t row = mrow0 + wm * 32 + t * 16 + (lane >> 2);
        #pragma unroll
        for (int n = 0; n < 8; n++) {
            int col = ncol0 + wn * 64 + n * 8 + (lane & 3) * 2;
            float2 b2 = *(const float2*)(bias - ncol0 + col);
            float2 o0 = { acc[t][n][0] + b2.x, acc[t][n][1] + b2.y };
            float2 o1 = { acc[t][n][2] + b2.x, acc[t][n][3] + b2.y };
            *(float2*)(outp + row * DIMV + col) = o0;
            *(float2*)(outp + (row + 8) * DIMV + col) = o1;
        }
    }
}

// ---------------- skinny gate GEMM: G[M,32] = A[M,512] @ Wg[512,32] ----------------
__global__ void gate_gemm(const float* __restrict__ A, const float* __restrict__ Wg,
                          float* __restrict__ G) {
    int row = blockIdx.x * 8 + (threadIdx.x >> 5);
    int col = threadIdx.x & 31;
    const float* a = A + (size_t)row * DIMV;
    float acc = 0.f;
    #pragma unroll 4
    for (int k = 0; k < DIMV; k += 4) {
        float4 a4 = *(const float4*)(a + k);
        acc += a4.x * Wg[(k + 0) * RANKV + col];
        acc += a4.y * Wg[(k + 1) * RANKV + col];
        acc += a4.z * Wg[(k + 2) * RANKV + col];
        acc += a4.w * Wg[(k + 3) * RANKV + col];
    }
    G[(size_t)row * RANKV + col] = acc;
}

// ---------------- block-sparse attention: one CTA per (b, q-step) ----------------
__global__ void attn_kernel(const float* __restrict__ mask) {
    int qs = blockIdx.x;   // 0..63
    int bb = blockIdx.y;   // 0..7
    int tid = threadIdx.x; // 256
    __shared__ float sc[16][MAXNK];
    __shared__ int s_lo, s_hi;
    if (tid == 0) { s_lo = 256; s_hi = -1; }
    __syncthreads();
    {
        float mv = mask[(size_t)(qs * 16) * KROWS + tid * 16];
        if (mv == 0.0f) { atomicMin(&s_lo, tid); atomicMax(&s_hi, tid); }
    }
    __syncthreads();
    int kbase = s_lo * 16;
    int nk = (s_hi - s_lo + 1) * 16;   // <= 144

    const float* qp = g_qp + ((size_t)bb * QROWS + qs * 16) * DIMV;
    const float* kp = g_kp + ((size_t)bb * KROWS + kbase) * DIMV;
    const float* gq = g_gq + ((size_t)bb * QROWS + qs * 16) * RANKV;
    const float* gk = g_gk + ((size_t)bb * KROWS + kbase) * RANKV;
    int tx = tid & 15, ty = tid >> 4;
    const float SCALE = 0.04419417382415922f;   // 512^-0.5
    const float GSCALE = 0.17677669529663687f;  // 32^-0.5

    const float* qrow = qp + ty * DIMV;
    const float* grow = gq + ty * RANKV;
    for (int kj = tx; kj < nk; kj += 16) {
        const float* krow = kp + (size_t)kj * DIMV;
        float s = 0.f;
        #pragma unroll 4
        for (int k = 0; k < DIMV; k += 4) {
            float4 q4 = *(const float4*)(qrow + k);
            float4 k4 = *(const float4*)(krow + k);
            s += q4.x * k4.x + q4.y * k4.y + q4.z * k4.z + q4.w * k4.w;
        }
        const float* gkr = gk + kj * RANKV;
        float gl = 0.f;
        #pragma unroll
        for (int r = 0; r < RANKV; r += 4) {
            float4 a4 = *(const float4*)(grow + r);
            float4 b4 = *(const float4*)(gkr + r);
            gl += a4.x * b4.x + a4.y * b4.y + a4.z * b4.z + a4.w * b4.w;
        }
        gl *= GSCALE;
        float sig = 1.f / (1.f + expf(-gl));
        sc[ty][kj] = s * SCALE + logf(sig + 1e-6f);
    }
    __syncthreads();

    float m = -1e30f;
    for (int kj = tx; kj < nk; kj += 16) m = fmaxf(m, sc[ty][kj]);
    #pragma unroll
    for (int o = 8; o; o >>= 1) m = fmaxf(m, __shfl_xor_sync(0xffffffffu, m, o, 16));
    float sum = 0.f;
    for (int kj = tx; kj < nk; kj += 16) {
        float e = expf(sc[ty][kj] - m);
        sc[ty][kj] = e;
        sum += e;
    }
    #pragma unroll
    for (int o = 8; o; o >>= 1) sum += __shfl_xor_sync(0xffffffffu, sum, o, 16);
    float inv = 1.f / sum;
    for (int kj = tx; kj < nk; kj += 16) sc[ty][kj] *= inv;
    __syncthreads();

    const float* vp = g_vp + ((size_t)bb * KROWS + kbase) * DIMV;
    float acc0[16], acc1[16];
    #pragma unroll
    for (int i = 0; i < 16; i++) { acc0[i] = 0.f; acc1[i] = 0.f; }
    int d0 = tid, d1 = tid + 256;
    for (int kj = 0; kj < nk; kj++) {
        float v0 = vp[(size_t)kj * DIMV + d0];
        float v1 = vp[(size_t)kj * DIMV + d1];
        #pragma unroll
        for (int qi = 0; qi < 16; qi++) {
            float p = sc[qi][kj];
            acc0[qi] += p * v0;
            acc1[qi] += p * v1;
        }
    }
    __nv_bfloat16* chi = g_chi + ((size_t)bb * QROWS + qs * 16) * DIMV;
    __nv_bfloat16* clo = g_clo + ((size_t)bb * QROWS + qs * 16) * DIMV;
    #pragma unroll
    for (int qi = 0; qi < 16; qi++) {
        float v = acc0[qi];
        __nv_bfloat16 h = __float2bfloat16(v);
        chi[(size_t)qi * DIMV + d0] = h;
        clo[(size_t)qi * DIMV + d0] = __float2bfloat16(v - __bfloat162float(h));
        v = acc1[qi];
        h = __float2bfloat16(v);
        chi[(size_t)qi * DIMV + d1] = h;
        clo[(size_t)qi * DIMV + d1] = __float2bfloat16(v - __bfloat162float(h));
    }
}

extern "C" void kernel_launch(void* const* d_in, const int* in_sizes, int n_in,
                              void* d_out, int out_size) {
    const float* query = (const float*)d_in[0];
    const float* source = (const float*)d_in[1];
    const float* ctx0  = (const float*)d_in[2];
    const float* ctx1  = (const float*)d_in[3];
    const float* mask  = (const float*)d_in[4];
    const float* qn_g  = (const float*)d_in[5];
    const float* qn_b  = (const float*)d_in[6];
    const float* kvn_g = (const float*)d_in[7];
    const float* kvn_b = (const float*)d_in[8];
    const float* Wq = (const float*)d_in[9];
    const float* bq = (const float*)d_in[10];
    const float* Wk = (const float*)d_in[11];
    const float* bk = (const float*)d_in[12];
    const float* Wv = (const float*)d_in[13];
    const float* bv = (const float*)d_in[14];
    const float* Wo = (const float*)d_in[15];
    const float* bo = (const float*)d_in[16];
    const float* Wgq = (const float*)d_in[17];
    const float* Wgk = (const float*)d_in[18];
    const float* Wc0 = (const float*)d_in[19];
    const float* bc0 = (const float*)d_in[20];
    const float* Wc1 = (const float*)d_in[21];
    const float* bc1 = (const float*)d_in[22];
    const float* Wf = (const float*)d_in[23];
    const float* bf = (const float*)d_in[24];
    float* out = (float*)d_out;

    __nv_bfloat16 *qhi, *qlo, *shi, *slo, *chi, *clo, *wthi, *wtlo;
    float *qp, *kp, *vp, *gq, *gk;
    cudaGetSymbolAddress((void**)&qhi, g_qhi);
    cudaGetSymbolAddress((void**)&qlo, g_qlo);
    cudaGetSymbolAddress((void**)&shi, g_shi);
    cudaGetSymbolAddress((void**)&slo, g_slo);
    cudaGetSymbolAddress((void**)&chi, g_chi);
    cudaGetSymbolAddress((void**)&clo, g_clo);
    cudaGetSymbolAddress((void**)&wthi, g_wthi);
    cudaGetSymbolAddress((void**)&wtlo, g_wtlo);
    cudaGetSymbolAddress((void**)&qp, g_qp);
    cudaGetSymbolAddress((void**)&kp, g_kp);
    cudaGetSymbolAddress((void**)&vp, g_vp);
    cudaGetSymbolAddress((void**)&gq, g_gq);
    cudaGetSymbolAddress((void**)&gk, g_gk);

    cudaFuncSetAttribute(mma_gemm, cudaFuncAttributeMaxDynamicSharedMemorySize, GEMM_SMEM);

    const size_t WSZ = (size_t)DIMV * DIMV;

    // 1. weight transpose+split and FiLM head (independent)
    wsplit_kernel<<<dim3(16, 16, 4), dim3(32, 8)>>>(Wq, Wk, Wv, Wo);
    ctx_kernel<<<BATCH, DIMV>>>(ctx0, ctx1, Wc0, bc0, Wc1, bc1, Wf, bf);
    // 2. LayerNorms -> bf16 hi/lo
    ln_kernel<<<BATCH * QROWS, 256>>>(query, qn_g, qn_b, qhi, qlo, 1);
    ln_kernel<<<BATCH * KROWS, 256>>>(source, kvn_g, kvn_b, shi, slo, 0);
    // 3. Q,K,V projections (mma.sync bf16x3); tiles = Mtiles*4
    mma_gemm<<<2304, 256, GEMM_SMEM>>>(
        qhi, qlo, wthi + 0 * WSZ, wtlo + 0 * WSZ, bq, qp, 256,
        shi, slo, wthi + 1 * WSZ, wtlo + 1 * WSZ, bk, kp, 1024,
        shi, slo, wthi + 2 * WSZ, wtlo + 2 * WSZ, bv, vp);
    // 4. Gate projections
    gate_gemm<<<BATCH * QROWS / 8, 256>>>(qp, Wgq, gq);
    gate_gemm<<<BATCH * KROWS / 8, 256>>>(kp, Wgk, gk);
    // 5. Block-sparse attention (writes ctx hi/lo)
    attn_kernel<<<dim3(64, BATCH), 256>>>(mask);
    // 6. Output projection
    mma_gemm<<<256, 256, GEMM_SMEM>>>(
        chi, clo, wthi + 3 * WSZ, wtlo + 3 * WSZ, bo, out, 256,
        (const __nv_bfloat16*)0, (const __nv_bfloat16*)0,
        (const __nv_bfloat16*)0, (const __nv_bfloat16*)0, (const float*)0, (float*)0, 0,
        (const __nv_bfloat16*)0, (const __nv_bfloat16*)0,
        (const __nv_bfloat16*)0, (const __nv_bfloat16*)0, (const float*)0, (float*)0);
}